// round 2
// baseline (speedup 1.0000x reference)
#include <cuda_runtime.h>
#include <cstdint>
#include <cstddef>

#define BN 32
#define NT 256
#define DD 2048
#define KC 64
#define BIGF 1e30f

// ---------------- scratch (static device globals; no allocation) ----------------
__device__ float g_rinv[BN * NT];
__device__ float g_S[BN * NT * NT];      // 8 MB
__device__ float g_Dm[BN * NT * NT];     // 8 MB
__device__ float g_sq[BN * NT];
__device__ float g_salmass[BN * NT];
__device__ int   g_order[BN * NT];
__device__ int   g_ccnt[BN * KC];
__device__ int   g_coff[BN * KC];
__device__ float g_maskdump[BN * NT];

// ---------------- 1: reciprocal row norms ----------------
__global__ void rnorm_kernel(const float* __restrict__ X) {
    int row = blockIdx.x * 8 + (threadIdx.x >> 5);
    int lane = threadIdx.x & 31;
    const float* x = X + (size_t)row * DD;
    float s = 0.f;
    for (int c = lane * 4; c < DD; c += 128) {
        float4 v = *(const float4*)&x[c];
        s += v.x * v.x + v.y * v.y + v.z * v.z + v.w * v.w;
    }
    #pragma unroll
    for (int o = 16; o; o >>= 1) s += __shfl_down_sync(0xffffffffu, s, o);
    if (lane == 0) g_rinv[row] = 1.0f / fmaxf(sqrtf(s), 1e-12f);
}

// ---------------- 2: fp32 GEMM (128x128 tile, 8x8 microtile) ----------------
// MODE 0: S = Xn @ Xn^T (per-row scaling by rinv at smem fill)
// MODE 1: T = S @ S^T with Dm epilogue: Dm = sqrt(max(sq_r + sq_c - 2T, 0)), diag=BIG
template <int MODE>
__global__ __launch_bounds__(256) void gemm128(const float* __restrict__ Ain) {
    constexpr int LD = (MODE == 0) ? DD : NT;
    constexpr int KD = LD;
    int b = blockIdx.y;
    int t3 = blockIdx.x;                 // 0:(0,0) 1:(0,1) 2:(1,1) upper-tri tiles
    int tr = (t3 == 2) ? 1 : 0;
    int tc = (t3 == 0) ? 0 : 1;
    const float* A = ((MODE == 0) ? Ain : g_S) + (size_t)b * NT * LD;

    __shared__ __align__(16) float As[16][132];
    __shared__ __align__(16) float Bs[16][132];

    int tid = threadIdx.x;
    int lrow = tid >> 1;                 // 0..127
    int lk = (tid & 1) * 8;              // 0 or 8
    int tm = (tid & 15) * 8;
    int tn = (tid >> 4) * 8;

    float sa = 1.f, sb = 1.f;
    if (MODE == 0) {
        sa = g_rinv[b * NT + tr * 128 + lrow];
        sb = g_rinv[b * NT + tc * 128 + lrow];
    }

    float acc[8][8];
    #pragma unroll
    for (int i = 0; i < 8; i++)
        #pragma unroll
        for (int j = 0; j < 8; j++) acc[i][j] = 0.f;

    const float* Arow = A + (size_t)(tr * 128 + lrow) * LD + lk;
    const float* Brow = A + (size_t)(tc * 128 + lrow) * LD + lk;

    for (int k0 = 0; k0 < KD; k0 += 16) {
        float4 a0 = *(const float4*)(Arow + k0);
        float4 a1 = *(const float4*)(Arow + k0 + 4);
        float4 b0 = *(const float4*)(Brow + k0);
        float4 b1 = *(const float4*)(Brow + k0 + 4);
        if (MODE == 0) {
            a0.x *= sa; a0.y *= sa; a0.z *= sa; a0.w *= sa;
            a1.x *= sa; a1.y *= sa; a1.z *= sa; a1.w *= sa;
            b0.x *= sb; b0.y *= sb; b0.z *= sb; b0.w *= sb;
            b1.x *= sb; b1.y *= sb; b1.z *= sb; b1.w *= sb;
        }
        As[lk + 0][lrow] = a0.x; As[lk + 1][lrow] = a0.y;
        As[lk + 2][lrow] = a0.z; As[lk + 3][lrow] = a0.w;
        As[lk + 4][lrow] = a1.x; As[lk + 5][lrow] = a1.y;
        As[lk + 6][lrow] = a1.z; As[lk + 7][lrow] = a1.w;
        Bs[lk + 0][lrow] = b0.x; Bs[lk + 1][lrow] = b0.y;
        Bs[lk + 2][lrow] = b0.z; Bs[lk + 3][lrow] = b0.w;
        Bs[lk + 4][lrow] = b1.x; Bs[lk + 5][lrow] = b1.y;
        Bs[lk + 6][lrow] = b1.z; Bs[lk + 7][lrow] = b1.w;
        __syncthreads();
        #pragma unroll
        for (int kk = 0; kk < 16; kk++) {
            float av[8], bv[8];
            *(float4*)&av[0] = *(const float4*)&As[kk][tm];
            *(float4*)&av[4] = *(const float4*)&As[kk][tm + 4];
            *(float4*)&bv[0] = *(const float4*)&Bs[kk][tn];
            *(float4*)&bv[4] = *(const float4*)&Bs[kk][tn + 4];
            #pragma unroll
            for (int i = 0; i < 8; i++)
                #pragma unroll
                for (int j = 0; j < 8; j++) acc[i][j] += av[i] * bv[j];
        }
        __syncthreads();
    }

    if (MODE == 0) {
        float* S = g_S + (size_t)b * NT * NT;
        #pragma unroll
        for (int i = 0; i < 8; i++) {
            int r = tr * 128 + tm + i;
            #pragma unroll
            for (int j = 0; j < 8; j++) {
                int c = tc * 128 + tn + j;
                S[r * NT + c] = acc[i][j];
                if (tr != tc) S[c * NT + r] = acc[i][j];
            }
        }
    } else {
        float* Dmp = g_Dm + (size_t)b * NT * NT;
        float sqr[8], sqc[8];
        #pragma unroll
        for (int i = 0; i < 8; i++) {
            sqr[i] = g_sq[b * NT + tr * 128 + tm + i];
            sqc[i] = g_sq[b * NT + tc * 128 + tn + i];
        }
        #pragma unroll
        for (int i = 0; i < 8; i++) {
            int r = tr * 128 + tm + i;
            #pragma unroll
            for (int j = 0; j < 8; j++) {
                int c = tc * 128 + tn + j;
                float d2 = sqr[i] + sqc[j] - 2.f * acc[i][j];
                float dm = sqrtf(fmaxf(d2, 0.f));
                if (r == c) dm = BIGF;
                Dmp[r * NT + c] = dm;
                if (tr != tc) Dmp[c * NT + r] = dm;
            }
        }
    }
}

// ---------------- 3: row sums of squares of S ----------------
__global__ void sq_kernel() {
    int b = blockIdx.x, t = threadIdx.x;
    const float* S = g_S + (size_t)b * NT * NT + (size_t)t * NT;
    float s = 0.f;
    for (int c = 0; c < NT; c += 4) {
        float4 v = *(const float4*)&S[c];
        s += v.x * v.x + v.y * v.y + v.z * v.z + v.w * v.w;
    }
    g_sq[b * NT + t] = s;
}

// ---------------- 4: clustering (one block per batch) ----------------
__device__ __forceinline__ void row_scan(const float* __restrict__ row,
                                         const unsigned char* __restrict__ act,
                                         int r, float& bv, int& bi) {
    int lane = threadIdx.x & 31;
    float v = BIGF; int idx = 1 << 20;
    #pragma unroll
    for (int c = lane; c < NT; c += 32) {
        float d = row[c];
        if (act[c] && c != r && d < v) { v = d; idx = c; }   // strict < keeps smallest col
    }
    #pragma unroll
    for (int o = 16; o; o >>= 1) {
        float ov = __shfl_down_sync(0xffffffffu, v, o);
        int oi = __shfl_down_sync(0xffffffffu, idx, o);
        if (ov < v || (ov == v && oi < idx)) { v = ov; idx = oi; }
    }
    bv = v; bi = idx;
}

__global__ __launch_bounds__(256) void cluster_kernel() {
    const int b = blockIdx.x;
    float* Dm = g_Dm + (size_t)b * NT * NT;
    const int t = threadIdx.x;
    const int lane = t & 31, wid = t >> 5;

    __shared__ float s_minv[NT];
    __shared__ short s_mini[NT];
    __shared__ float s_size[NT];
    __shared__ unsigned char s_active[NT];
    __shared__ short s_label[NT];
    __shared__ float s_rv[8];
    __shared__ int   s_ri[8];
    __shared__ int   s_bi, s_bj;
    __shared__ int   s_recount;
    __shared__ short s_relist[NT];

    s_active[t] = 1; s_size[t] = 1.f; s_label[t] = (short)t;
    __syncthreads();

    // initial per-row nearest neighbor (warp per row)
    for (int r = wid; r < NT; r += 8) {
        float v; int i2;
        row_scan(Dm + (size_t)r * NT, s_active, r, v, i2);
        if (lane == 0) { s_minv[r] = v; s_mini[r] = (short)i2; }
    }
    __syncthreads();

    for (int it = 0; it < NT - KC; ++it) {
        // global argmin over rowmins (tie: smallest row)
        float v = s_minv[t]; int r = t;
        #pragma unroll
        for (int o = 16; o; o >>= 1) {
            float ov = __shfl_down_sync(0xffffffffu, v, o);
            int orr = __shfl_down_sync(0xffffffffu, r, o);
            if (ov < v || (ov == v && orr < r)) { v = ov; r = orr; }
        }
        if (lane == 0) { s_rv[wid] = v; s_ri[wid] = r; }
        __syncthreads();
        if (t == 0) {
            float bv = s_rv[0]; int br = s_ri[0];
            #pragma unroll
            for (int w = 1; w < 8; w++)
                if (s_rv[w] < bv || (s_rv[w] == bv && s_ri[w] < br)) { bv = s_rv[w]; br = s_ri[w]; }
            s_bi = br; s_bj = s_mini[br];
            s_recount = 0;
        }
        __syncthreads();
        int i = s_bi, j = s_bj;               // i < j guaranteed
        float si = s_size[i], sj = s_size[j];
        float di = Dm[(size_t)i * NT + t];
        float dj = Dm[(size_t)j * NT + t];
        __syncthreads();                       // all reads done before writes
        float nv = (si * di + sj * dj) / (si + sj);
        if (t == i) nv = BIGF;
        Dm[(size_t)i * NT + t] = nv;
        Dm[(size_t)t * NT + i] = nv;
        if (t == 0) { s_size[i] = si + sj; s_active[j] = 0; s_minv[j] = BIGF; }
        if (s_label[t] == (short)j) s_label[t] = (short)i;
        __syncthreads();                       // Dm writes + state visible

        // rowmin maintenance
        if (t == i) {
            int p = atomicAdd(&s_recount, 1); s_relist[p] = (short)t;
        } else if (t != j && s_active[t]) {
            float mv = s_minv[t]; int mi = s_mini[t];
            if (mi == i || mi == j) {
                if (nv < mv) { s_minv[t] = nv; s_mini[t] = (short)i; }
                else { int p = atomicAdd(&s_recount, 1); s_relist[p] = (short)t; }
            } else if (nv < mv || (nv == mv && i < mi)) {
                s_minv[t] = nv; s_mini[t] = (short)i;
            }
        }
        __syncthreads();
        int rc = s_recount;
        for (int e = wid; e < rc; e += 8) {
            int r2 = s_relist[e];
            float v2; int i2;
            row_scan(Dm + (size_t)r2 * NT, s_active, r2, v2, i2);
            if (lane == 0) { s_minv[r2] = v2; s_mini[r2] = (short)i2; }
        }
        __syncthreads();
    }

    // canonical relabel: new_id = cumsum(active)-1
    __shared__ short s_newid[NT];
    __shared__ short s_flab[NT];
    __shared__ short s_cnt[KC];
    __shared__ short s_off[KC];
    {
        int c = 0;
        for (int r2 = 0; r2 <= t; ++r2) c += s_active[r2];
        s_newid[t] = (short)(c - 1);
    }
    __syncthreads();
    int fl = s_newid[s_label[t]];
    s_flab[t] = (short)fl;
    __syncthreads();
    if (t < KC) {
        int cnt = 0;
        for (int r2 = 0; r2 < NT; r2++) cnt += (s_flab[r2] == (short)t);
        s_cnt[t] = (short)cnt;
        g_ccnt[b * KC + t] = cnt;
    }
    __syncthreads();
    if (t < KC) {
        int off = 0;
        for (int k2 = 0; k2 < t; k2++) off += s_cnt[k2];
        s_off[t] = (short)off;
        g_coff[b * KC + t] = off;
    }
    __syncthreads();
    {
        int rank = 0;
        for (int r2 = 0; r2 < t; r2++) rank += (s_flab[r2] == (short)fl);
        g_order[b * NT + s_off[fl] + rank] = t;
    }
}

// ---------------- 5: mask (softmax) + sal_mass ----------------
__global__ void mask_kernel(const float* __restrict__ sal,
                            const float* __restrict__ gum,
                            float* __restrict__ mout) {
    int b = blockIdx.x, t = threadIdx.x;
    float s = sal[b * NT + t];
    float l = (s + gum[b * NT + t]) / 0.1f;
    __shared__ float red[8];
    float m = l;
    #pragma unroll
    for (int o = 16; o; o >>= 1) m = fmaxf(m, __shfl_xor_sync(0xffffffffu, m, o));
    if ((t & 31) == 0) red[t >> 5] = m;
    __syncthreads();
    float mx = red[0];
    #pragma unroll
    for (int w = 1; w < 8; w++) mx = fmaxf(mx, red[w]);
    float e = expf(l - mx);
    float sm = e;
    #pragma unroll
    for (int o = 16; o; o >>= 1) sm += __shfl_xor_sync(0xffffffffu, sm, o);
    __syncthreads();
    if ((t & 31) == 0) red[t >> 5] = sm;
    __syncthreads();
    float tot = 0.f;
    #pragma unroll
    for (int w = 0; w < 8; w++) tot += red[w];
    float mk = e / tot;
    mout[b * NT + t] = mk;
    g_salmass[b * NT + t] = mk * s + (1.f - mk) * 0.01f;
}

// ---------------- 6: saliency-weighted per-cluster merge ----------------
__global__ __launch_bounds__(256) void merge_kernel(const float* __restrict__ X,
                                                    float* __restrict__ out) {
    int b = blockIdx.x >> 6;
    int k = blockIdx.x & 63;
    int cnt = g_ccnt[b * KC + k];
    int off = g_coff[b * KC + k];
    int t = threadIdx.x;
    int d0 = t * 8;
    float acc[8] = {0.f, 0.f, 0.f, 0.f, 0.f, 0.f, 0.f, 0.f};
    float den = 0.f;
    for (int e = 0; e < cnt; ++e) {
        int tok = g_order[b * NT + off + e];
        float w = g_salmass[b * NT + tok];
        den += w;
        const float4* xp = (const float4*)(X + ((size_t)(b * NT + tok) * DD + d0));
        float4 x0 = xp[0], x1 = xp[1];
        acc[0] += w * x0.x; acc[1] += w * x0.y; acc[2] += w * x0.z; acc[3] += w * x0.w;
        acc[4] += w * x1.x; acc[5] += w * x1.y; acc[6] += w * x1.z; acc[7] += w * x1.w;
    }
    float d = den + 1e-8f;
    float4 o0, o1;
    o0.x = acc[0] / d; o0.y = acc[1] / d; o0.z = acc[2] / d; o0.w = acc[3] / d;
    o1.x = acc[4] / d; o1.y = acc[5] / d; o1.z = acc[6] / d; o1.w = acc[7] / d;
    float4* op = (float4*)(out + ((size_t)(b * KC + k) * DD + d0));
    op[0] = o0; op[1] = o1;
}

// ---------------- launch ----------------
extern "C" void kernel_launch(void* const* d_in, const int* in_sizes, int n_in,
                              void* d_out, int out_size) {
    const float* X = (const float*)d_in[0];
    const float* sal = (const float*)d_in[1];
    const float* gum = (const float*)d_in[2];
    float* out = (float*)d_out;

    const int MERGED = BN * KC * DD;           // 4,194,304
    float* mask_out;
    if (out_size >= MERGED + BN * NT) {
        mask_out = out + MERGED;
    } else {
        // output carries only 'merged'; dump mask to scratch
        cudaError_t e; void* p = nullptr;
        e = cudaGetSymbolAddress(&p, g_maskdump);
        (void)e;
        mask_out = (float*)p;
    }

    rnorm_kernel<<<BN * NT / 8, 256>>>(X);
    gemm128<0><<<dim3(3, BN), 256>>>(X);
    sq_kernel<<<BN, 256>>>();
    gemm128<1><<<dim3(3, BN), 256>>>(nullptr);
    cluster_kernel<<<BN, 256>>>();
    mask_kernel<<<BN, 256>>>(sal, gum, mask_out);
    merge_kernel<<<BN * KC, 256>>>(X, out);
}

// round 3
// speedup vs baseline: 1.0966x; 1.0966x over previous
#include <cuda_runtime.h>
#include <cstdint>
#include <cstddef>

#define BN 32
#define NT 256
#define DD 2048
#define KC 64
#define BIGF 1e30f

// ---------------- scratch (static device globals; no allocation) ----------------
__device__ float g_rinv[BN * NT];
__device__ float g_S[BN * NT * NT];      // 8 MB
__device__ float g_Dm[BN * NT * NT];     // 8 MB
__device__ float g_sq[BN * NT];
__device__ float g_salmass[BN * NT];
__device__ int   g_order[BN * NT];
__device__ int   g_ccnt[BN * KC];
__device__ int   g_coff[BN * KC];
__device__ float g_maskdump[BN * NT];

// ---------------- 1: reciprocal row norms ----------------
__global__ void rnorm_kernel(const float* __restrict__ X) {
    int row = blockIdx.x * 8 + (threadIdx.x >> 5);
    int lane = threadIdx.x & 31;
    const float* x = X + (size_t)row * DD;
    float s = 0.f;
    for (int c = lane * 4; c < DD; c += 128) {
        float4 v = *(const float4*)&x[c];
        s += v.x * v.x + v.y * v.y + v.z * v.z + v.w * v.w;
    }
    #pragma unroll
    for (int o = 16; o; o >>= 1) s += __shfl_down_sync(0xffffffffu, s, o);
    if (lane == 0) g_rinv[row] = 1.0f / fmaxf(sqrtf(s), 1e-12f);
}

// ---------------- 2: fp32 GEMM with packed f32x2 FMA ----------------
// MODE 0: S = Xn @ Xn^T (per-row scaling by rinv at load)
// MODE 1: T = S @ S^T with Dm epilogue: Dm = sqrt(max(sq_r + sq_c - 2T, 0)), diag=BIG
// 128x128 tile, 256 threads, 8x8 microtile split as row groups {g*4, 64+g*4},
// col groups {h*4, 64+h*4}. Accumulators are f32x2 pairs along columns.
template <int MODE>
__global__ __launch_bounds__(256) void gemm128(const float* __restrict__ Ain) {
    constexpr int LD = (MODE == 0) ? DD : NT;
    constexpr int KD = LD;
    int b = blockIdx.y;
    int t3 = blockIdx.x;                 // 0:(0,0) 1:(0,1) 2:(1,1) upper-tri tiles
    int tr = (t3 == 2) ? 1 : 0;
    int tc = (t3 == 0) ? 0 : 1;
    const float* A = ((MODE == 0) ? Ain : g_S) + (size_t)b * NT * LD;

    __shared__ __align__(16) float As[2][8][132];
    __shared__ __align__(16) float Bs[2][8][132];

    int tid = threadIdx.x;
    int frow = tid & 127;                // fill: row within tile
    int fk = (tid >> 7) * 4;             // fill: k offset 0 or 4
    int g = tid & 15;                    // micro row group
    int h = tid >> 4;                    // micro col group

    float sa = 1.f, sb = 1.f;
    if (MODE == 0) {
        sa = g_rinv[b * NT + tr * 128 + frow];
        sb = g_rinv[b * NT + tc * 128 + frow];
    }

    unsigned long long accd[8][4];
    #pragma unroll
    for (int i = 0; i < 8; i++)
        #pragma unroll
        for (int jp = 0; jp < 4; jp++) accd[i][jp] = 0ULL;

    const float* Ag = A + (size_t)(tr * 128 + frow) * LD;
    const float* Bg = A + (size_t)(tc * 128 + frow) * LD;

    // prologue: chunk 0
    {
        float4 fa = *(const float4*)(Ag + fk);
        float4 fb = *(const float4*)(Bg + fk);
        if (MODE == 0) {
            fa.x *= sa; fa.y *= sa; fa.z *= sa; fa.w *= sa;
            fb.x *= sb; fb.y *= sb; fb.z *= sb; fb.w *= sb;
        }
        As[0][fk + 0][frow] = fa.x; As[0][fk + 1][frow] = fa.y;
        As[0][fk + 2][frow] = fa.z; As[0][fk + 3][frow] = fa.w;
        Bs[0][fk + 0][frow] = fb.x; Bs[0][fk + 1][frow] = fb.y;
        Bs[0][fk + 2][frow] = fb.z; Bs[0][fk + 3][frow] = fb.w;
    }
    __syncthreads();

    int cur = 0;
    for (int k0 = 8; k0 < KD + 8; k0 += 8) {
        bool has = (k0 < KD);
        float4 na, nb;
        if (has) {
            na = *(const float4*)(Ag + k0 + fk);
            nb = *(const float4*)(Bg + k0 + fk);
            if (MODE == 0) {
                na.x *= sa; na.y *= sa; na.z *= sa; na.w *= sa;
                nb.x *= sb; nb.y *= sb; nb.z *= sb; nb.w *= sb;
            }
        }
        // compute current chunk
        #pragma unroll
        for (int kk = 0; kk < 8; kk++) {
            float a4[8];
            *(float4*)&a4[0] = *(const float4*)&As[cur][kk][g * 4];
            *(float4*)&a4[4] = *(const float4*)&As[cur][kk][64 + g * 4];
            ulonglong2 b01 = *(const ulonglong2*)&Bs[cur][kk][h * 4];
            ulonglong2 b23 = *(const ulonglong2*)&Bs[cur][kk][64 + h * 4];
            unsigned long long bq0 = b01.x, bq1 = b01.y, bq2 = b23.x, bq3 = b23.y;
            #pragma unroll
            for (int i = 0; i < 8; i++) {
                unsigned int au = __float_as_uint(a4[i]);
                unsigned long long ad;
                asm("mov.b64 %0, {%1, %1};" : "=l"(ad) : "r"(au));
                asm("fma.rn.f32x2 %0, %1, %2, %0;" : "+l"(accd[i][0]) : "l"(ad), "l"(bq0));
                asm("fma.rn.f32x2 %0, %1, %2, %0;" : "+l"(accd[i][1]) : "l"(ad), "l"(bq1));
                asm("fma.rn.f32x2 %0, %1, %2, %0;" : "+l"(accd[i][2]) : "l"(ad), "l"(bq2));
                asm("fma.rn.f32x2 %0, %1, %2, %0;" : "+l"(accd[i][3]) : "l"(ad), "l"(bq3));
            }
        }
        if (has) {
            int alt = cur ^ 1;
            As[alt][fk + 0][frow] = na.x; As[alt][fk + 1][frow] = na.y;
            As[alt][fk + 2][frow] = na.z; As[alt][fk + 3][frow] = na.w;
            Bs[alt][fk + 0][frow] = nb.x; Bs[alt][fk + 1][frow] = nb.y;
            Bs[alt][fk + 2][frow] = nb.z; Bs[alt][fk + 3][frow] = nb.w;
            __syncthreads();
            cur = alt;
        }
    }

    // unpack accumulators
    float accf[8][8];
    #pragma unroll
    for (int i = 0; i < 8; i++)
        #pragma unroll
        for (int jp = 0; jp < 4; jp++) {
            unsigned int lo, hi;
            asm("mov.b64 {%0, %1}, %2;" : "=r"(lo), "=r"(hi) : "l"(accd[i][jp]));
            accf[i][2 * jp]     = __uint_as_float(lo);
            accf[i][2 * jp + 1] = __uint_as_float(hi);
        }

    int rows[8], cols[8];
    #pragma unroll
    for (int q = 0; q < 4; q++) {
        rows[q]     = tr * 128 + g * 4 + q;
        rows[q + 4] = tr * 128 + 64 + g * 4 + q;
        cols[q]     = tc * 128 + h * 4 + q;
        cols[q + 4] = tc * 128 + 64 + h * 4 + q;
    }

    if (MODE == 0) {
        float* S = g_S + (size_t)b * NT * NT;
        #pragma unroll
        for (int i = 0; i < 8; i++) {
            int r = rows[i];
            float4 v0 = {accf[i][0], accf[i][1], accf[i][2], accf[i][3]};
            float4 v1 = {accf[i][4], accf[i][5], accf[i][6], accf[i][7]};
            *(float4*)&S[r * NT + cols[0]] = v0;
            *(float4*)&S[r * NT + cols[4]] = v1;
            if (tr != tc) {
                #pragma unroll
                for (int j = 0; j < 8; j++) S[cols[j] * NT + r] = accf[i][j];
            }
        }
    } else {
        float* Dmp = g_Dm + (size_t)b * NT * NT;
        float sqr[8], sqc[8];
        #pragma unroll
        for (int i = 0; i < 8; i++) {
            sqr[i] = g_sq[b * NT + rows[i]];
            sqc[i] = g_sq[b * NT + cols[i]];
        }
        float dm[8][8];
        #pragma unroll
        for (int i = 0; i < 8; i++)
            #pragma unroll
            for (int j = 0; j < 8; j++) {
                float d2 = sqr[i] + sqc[j] - 2.f * accf[i][j];
                float v = sqrtf(fmaxf(d2, 0.f));
                if (rows[i] == cols[j]) v = BIGF;
                dm[i][j] = v;
            }
        #pragma unroll
        for (int i = 0; i < 8; i++) {
            int r = rows[i];
            float4 v0 = {dm[i][0], dm[i][1], dm[i][2], dm[i][3]};
            float4 v1 = {dm[i][4], dm[i][5], dm[i][6], dm[i][7]};
            *(float4*)&Dmp[r * NT + cols[0]] = v0;
            *(float4*)&Dmp[r * NT + cols[4]] = v1;
            if (tr != tc) {
                #pragma unroll
                for (int j = 0; j < 8; j++) Dmp[cols[j] * NT + r] = dm[i][j];
            }
        }
    }
}

// ---------------- 3: row sums of squares of S ----------------
__global__ void sq_kernel() {
    int b = blockIdx.x, t = threadIdx.x;
    const float* S = g_S + (size_t)b * NT * NT + (size_t)t * NT;
    float s = 0.f;
    for (int c = 0; c < NT; c += 4) {
        float4 v = *(const float4*)&S[c];
        s += v.x * v.x + v.y * v.y + v.z * v.z + v.w * v.w;
    }
    g_sq[b * NT + t] = s;
}

// ---------------- 4: clustering (one block per batch) ----------------
__device__ __forceinline__ void row_scan(const float* __restrict__ row,
                                         const unsigned char* __restrict__ act,
                                         int r, float& bv, int& bi) {
    int lane = threadIdx.x & 31;
    float v = BIGF; int idx = 1 << 20;
    #pragma unroll
    for (int c = lane; c < NT; c += 32) {
        float d = row[c];
        if (act[c] && c != r && d < v) { v = d; idx = c; }   // strict < keeps smallest col
    }
    #pragma unroll
    for (int o = 16; o; o >>= 1) {
        float ov = __shfl_down_sync(0xffffffffu, v, o);
        int oi = __shfl_down_sync(0xffffffffu, idx, o);
        if (ov < v || (ov == v && oi < idx)) { v = ov; idx = oi; }
    }
    bv = v; bi = idx;
}

__global__ __launch_bounds__(256) void cluster_kernel() {
    const int b = blockIdx.x;
    float* Dm = g_Dm + (size_t)b * NT * NT;
    const int t = threadIdx.x;
    const int lane = t & 31, wid = t >> 5;

    __shared__ float s_minv[NT];
    __shared__ short s_mini[NT];
    __shared__ float s_size[NT];
    __shared__ unsigned char s_active[NT];
    __shared__ short s_label[NT];
    __shared__ float s_wv[8];
    __shared__ int   s_wi[8];
    __shared__ int   s_bi, s_bj;
    __shared__ int   s_recount;
    __shared__ short s_relist[NT];

    s_active[t] = 1; s_size[t] = 1.f; s_label[t] = (short)t;
    __syncthreads();

    // initial per-row nearest neighbor (warp per row) — also warms L1 with Dm
    for (int r = wid; r < NT; r += 8) {
        float v; int i2;
        row_scan(Dm + (size_t)r * NT, s_active, r, v, i2);
        if (lane == 0) { s_minv[r] = v; s_mini[r] = (short)i2; }
    }
    __syncthreads();

    for (int it = 0; it < NT - KC; ++it) {
        // --- phase B: warp 0 global argmin over rowmins (tie: smallest row) ---
        if (wid == 0) {
            float bv = BIGF; int br = 1 << 20;
            #pragma unroll
            for (int r = lane; r < NT; r += 32) {
                float v = s_minv[r];
                if (v < bv) { bv = v; br = r; }   // r ascending per lane -> first kept
            }
            #pragma unroll
            for (int o = 16; o; o >>= 1) {
                float ov = __shfl_down_sync(0xffffffffu, bv, o);
                int orr = __shfl_down_sync(0xffffffffu, br, o);
                if (ov < bv || (ov == bv && orr < br)) { bv = ov; br = orr; }
            }
            if (lane == 0) { s_bi = br; s_bj = s_mini[br]; s_recount = 0; }
        }
        __syncthreads();                          // (1)

        int i = s_bi, j = s_bj;                   // i < j guaranteed (symmetry + tie-break)
        float si = s_size[i], sj = s_size[j];
        float di = Dm[(size_t)i * NT + t];
        float dj = Dm[(size_t)j * NT + t];
        __syncthreads();                          // (2) all reads done before writes

        float nv = (si * di + sj * dj) / (si + sj);
        if (t == i) nv = BIGF;
        Dm[(size_t)i * NT + t] = nv;
        Dm[(size_t)t * NT + i] = nv;
        if (s_label[t] == (short)j) s_label[t] = (short)i;

        // row i's new rowmin from nv (block reduce, tie smallest col)
        {
            float cv = (t != i && t != j && s_active[t]) ? nv : BIGF;
            int ci = t;
            #pragma unroll
            for (int o = 16; o; o >>= 1) {
                float ov = __shfl_down_sync(0xffffffffu, cv, o);
                int oi = __shfl_down_sync(0xffffffffu, ci, o);
                if (ov < cv || (ov == cv && oi < ci)) { cv = ov; ci = oi; }
            }
            if (lane == 0) { s_wv[wid] = cv; s_wi[wid] = ci; }
        }
        if (t == 0) { s_size[i] = si + sj; s_active[j] = 0; s_minv[j] = BIGF; }

        // rowmin maintenance for other rows
        if (t != i && t != j && s_active[t]) {
            float mv = s_minv[t]; int mi = s_mini[t];
            if (mi == i || mi == j) {
                if (nv < mv) { s_minv[t] = nv; s_mini[t] = (short)i; }
                else { int p = atomicAdd(&s_recount, 1); s_relist[p] = (short)t; }
            } else if (nv < mv || (nv == mv && i < mi)) {
                s_minv[t] = nv; s_mini[t] = (short)i;
            }
        }
        __syncthreads();                          // (3)

        if (t == 0) {
            float bv = s_wv[0]; int bi2 = s_wi[0];
            #pragma unroll
            for (int w = 1; w < 8; w++)
                if (s_wv[w] < bv || (s_wv[w] == bv && s_wi[w] < bi2)) { bv = s_wv[w]; bi2 = s_wi[w]; }
            s_minv[i] = bv; s_mini[i] = (short)bi2;
        }
        int rc = s_recount;
        for (int e = wid; e < rc; e += 8) {
            int r2 = s_relist[e];
            float v2; int i2;
            row_scan(Dm + (size_t)r2 * NT, s_active, r2, v2, i2);
            if (lane == 0) { s_minv[r2] = v2; s_mini[r2] = (short)i2; }
        }
        __syncthreads();                          // (4)
    }

    // canonical relabel: new_id = cumsum(active)-1
    __shared__ short s_newid[NT];
    __shared__ short s_flab[NT];
    __shared__ short s_cnt[KC];
    __shared__ short s_off[KC];
    {
        int c = 0;
        for (int r2 = 0; r2 <= t; ++r2) c += s_active[r2];
        s_newid[t] = (short)(c - 1);
    }
    __syncthreads();
    int fl = s_newid[s_label[t]];
    s_flab[t] = (short)fl;
    __syncthreads();
    if (t < KC) {
        int cnt = 0;
        for (int r2 = 0; r2 < NT; r2++) cnt += (s_flab[r2] == (short)t);
        s_cnt[t] = (short)cnt;
        g_ccnt[b * KC + t] = cnt;
    }
    __syncthreads();
    if (t < KC) {
        int off = 0;
        for (int k2 = 0; k2 < t; k2++) off += s_cnt[k2];
        s_off[t] = (short)off;
        g_coff[b * KC + t] = off;
    }
    __syncthreads();
    {
        int rank = 0;
        for (int r2 = 0; r2 < t; r2++) rank += (s_flab[r2] == (short)fl);
        g_order[b * NT + s_off[fl] + rank] = t;
    }
}

// ---------------- 5: mask (softmax) + sal_mass ----------------
__global__ void mask_kernel(const float* __restrict__ sal,
                            const float* __restrict__ gum,
                            float* __restrict__ mout) {
    int b = blockIdx.x, t = threadIdx.x;
    float s = sal[b * NT + t];
    float l = (s + gum[b * NT + t]) / 0.1f;
    __shared__ float red[8];
    float m = l;
    #pragma unroll
    for (int o = 16; o; o >>= 1) m = fmaxf(m, __shfl_xor_sync(0xffffffffu, m, o));
    if ((t & 31) == 0) red[t >> 5] = m;
    __syncthreads();
    float mx = red[0];
    #pragma unroll
    for (int w = 1; w < 8; w++) mx = fmaxf(mx, red[w]);
    float e = expf(l - mx);
    float sm = e;
    #pragma unroll
    for (int o = 16; o; o >>= 1) sm += __shfl_xor_sync(0xffffffffu, sm, o);
    __syncthreads();
    if ((t & 31) == 0) red[t >> 5] = sm;
    __syncthreads();
    float tot = 0.f;
    #pragma unroll
    for (int w = 0; w < 8; w++) tot += red[w];
    float mk = e / tot;
    mout[b * NT + t] = mk;
    g_salmass[b * NT + t] = mk * s + (1.f - mk) * 0.01f;
}

// ---------------- 6: saliency-weighted per-cluster merge ----------------
__global__ __launch_bounds__(256) void merge_kernel(const float* __restrict__ X,
                                                    float* __restrict__ out) {
    int b = blockIdx.x >> 6;
    int k = blockIdx.x & 63;
    int cnt = g_ccnt[b * KC + k];
    int off = g_coff[b * KC + k];
    int t = threadIdx.x;
    int d0 = t * 8;
    float acc[8] = {0.f, 0.f, 0.f, 0.f, 0.f, 0.f, 0.f, 0.f};
    float den = 0.f;
    for (int e = 0; e < cnt; ++e) {
        int tok = g_order[b * NT + off + e];
        float w = g_salmass[b * NT + tok];
        den += w;
        const float4* xp = (const float4*)(X + ((size_t)(b * NT + tok) * DD + d0));
        float4 x0 = xp[0], x1 = xp[1];
        acc[0] += w * x0.x; acc[1] += w * x0.y; acc[2] += w * x0.z; acc[3] += w * x0.w;
        acc[4] += w * x1.x; acc[5] += w * x1.y; acc[6] += w * x1.z; acc[7] += w * x1.w;
    }
    float d = den + 1e-8f;
    float4 o0, o1;
    o0.x = acc[0] / d; o0.y = acc[1] / d; o0.z = acc[2] / d; o0.w = acc[3] / d;
    o1.x = acc[4] / d; o1.y = acc[5] / d; o1.z = acc[6] / d; o1.w = acc[7] / d;
    float4* op = (float4*)(out + ((size_t)(b * KC + k) * DD + d0));
    op[0] = o0; op[1] = o1;
}

// ---------------- launch ----------------
extern "C" void kernel_launch(void* const* d_in, const int* in_sizes, int n_in,
                              void* d_out, int out_size) {
    const float* X = (const float*)d_in[0];
    const float* sal = (const float*)d_in[1];
    const float* gum = (const float*)d_in[2];
    float* out = (float*)d_out;

    const int MERGED = BN * KC * DD;           // 4,194,304
    float* mask_out;
    if (out_size >= MERGED + BN * NT) {
        mask_out = out + MERGED;
    } else {
        cudaError_t e; void* p = nullptr;
        e = cudaGetSymbolAddress(&p, g_maskdump);
        (void)e;
        mask_out = (float*)p;
    }

    rnorm_kernel<<<BN * NT / 8, 256>>>(X);
    gemm128<0><<<dim3(3, BN), 256>>>(X);
    sq_kernel<<<BN, 256>>>();
    gemm128<1><<<dim3(3, BN), 256>>>(nullptr);
    cluster_kernel<<<BN, 256>>>();
    mask_kernel<<<BN, 256>>>(sal, gum, mask_out);
    merge_kernel<<<BN * KC, 256>>>(X, out);
}

// round 5
// speedup vs baseline: 1.2372x; 1.1282x over previous
#include <cuda_runtime.h>
#include <cstdint>
#include <cstddef>

#define BN 32
#define NT 256
#define DD 2048
#define KC 64
#define BIGF 1e30f

// ---------------- scratch (static device globals; no allocation) ----------------
__device__ float g_rinv[BN * NT];
__device__ float g_S[BN * NT * NT];              // 8.4 MB
__device__ float g_Dm[BN * NT * NT];             // 8.4 MB
__device__ float g_part[4][BN * NT * NT];        // 33.6 MB split-K partials
__device__ float g_sq[BN * NT];
__device__ float g_salmass[BN * NT];
__device__ int   g_order[BN * NT];
__device__ int   g_ccnt[BN * KC];
__device__ int   g_coff[BN * KC];
__device__ float g_maskdump[BN * NT];

// ---------------- 1: reciprocal row norms ----------------
__global__ void rnorm_kernel(const float* __restrict__ X) {
    int row = blockIdx.x * 8 + (threadIdx.x >> 5);
    int lane = threadIdx.x & 31;
    const float* x = X + (size_t)row * DD;
    float s = 0.f;
    for (int c = lane * 4; c < DD; c += 128) {
        float4 v = *(const float4*)&x[c];
        s += v.x * v.x + v.y * v.y + v.z * v.z + v.w * v.w;
    }
    #pragma unroll
    for (int o = 16; o; o >>= 1) s += __shfl_down_sync(0xffffffffu, s, o);
    if (lane == 0) g_rinv[row] = 1.0f / fmaxf(sqrtf(s), 1e-12f);
}

// ---------------- 2: split-K fp32 GEMM with packed f32x2 FMA ----------------
// MODE 0: partial of Xn @ Xn^T   MODE 1: partial of S @ S^T
// 128x128 tile, 256 threads, 8x8 microtile; writes raw partial (with mirror)
// into g_part[blockIdx.z].
template <int MODE, int SPLIT>
__global__ __launch_bounds__(256, 2) void gemm128(const float* __restrict__ Ain) {
    constexpr int LD = (MODE == 0) ? DD : NT;
    constexpr int KP = LD / SPLIT;               // K per split
    int b = blockIdx.y;
    int t3 = blockIdx.x;                 // 0:(0,0) 1:(0,1) 2:(1,1) upper-tri tiles
    int tr = (t3 == 2) ? 1 : 0;
    int tc = (t3 == 0) ? 0 : 1;
    int koff = blockIdx.z * KP;
    const float* A = ((MODE == 0) ? Ain : g_S) + (size_t)b * NT * LD;
    float* P = g_part[blockIdx.z] + (size_t)b * NT * NT;

    __shared__ __align__(16) float As[2][8][132];
    __shared__ __align__(16) float Bs[2][8][132];

    int tid = threadIdx.x;
    int frow = tid & 127;                // fill: row within tile
    int fk = (tid >> 7) * 4;             // fill: k offset 0 or 4
    int g = tid & 15;                    // micro row group
    int h = tid >> 4;                    // micro col group

    float sa = 1.f, sb = 1.f;
    if (MODE == 0) {
        sa = g_rinv[b * NT + tr * 128 + frow];
        sb = g_rinv[b * NT + tc * 128 + frow];
    }

    unsigned long long accd[8][4];
    #pragma unroll
    for (int i = 0; i < 8; i++)
        #pragma unroll
        for (int jp = 0; jp < 4; jp++) accd[i][jp] = 0ULL;

    const float* Ag = A + (size_t)(tr * 128 + frow) * LD + koff;
    const float* Bg = A + (size_t)(tc * 128 + frow) * LD + koff;

    // prologue: chunk 0
    {
        float4 fa = *(const float4*)(Ag + fk);
        float4 fb = *(const float4*)(Bg + fk);
        if (MODE == 0) {
            fa.x *= sa; fa.y *= sa; fa.z *= sa; fa.w *= sa;
            fb.x *= sb; fb.y *= sb; fb.z *= sb; fb.w *= sb;
        }
        As[0][fk + 0][frow] = fa.x; As[0][fk + 1][frow] = fa.y;
        As[0][fk + 2][frow] = fa.z; As[0][fk + 3][frow] = fa.w;
        Bs[0][fk + 0][frow] = fb.x; Bs[0][fk + 1][frow] = fb.y;
        Bs[0][fk + 2][frow] = fb.z; Bs[0][fk + 3][frow] = fb.w;
    }
    __syncthreads();

    int cur = 0;
    for (int k0 = 8; k0 < KP + 8; k0 += 8) {
        bool has = (k0 < KP);
        float4 na, nb;
        if (has) {
            na = *(const float4*)(Ag + k0 + fk);
            nb = *(const float4*)(Bg + k0 + fk);
            if (MODE == 0) {
                na.x *= sa; na.y *= sa; na.z *= sa; na.w *= sa;
                nb.x *= sb; nb.y *= sb; nb.z *= sb; nb.w *= sb;
            }
        }
        #pragma unroll
        for (int kk = 0; kk < 8; kk++) {
            float a4[8];
            *(float4*)&a4[0] = *(const float4*)&As[cur][kk][g * 4];
            *(float4*)&a4[4] = *(const float4*)&As[cur][kk][64 + g * 4];
            ulonglong2 b01 = *(const ulonglong2*)&Bs[cur][kk][h * 4];
            ulonglong2 b23 = *(const ulonglong2*)&Bs[cur][kk][64 + h * 4];
            unsigned long long bq0 = b01.x, bq1 = b01.y, bq2 = b23.x, bq3 = b23.y;
            #pragma unroll
            for (int i = 0; i < 8; i++) {
                unsigned int au = __float_as_uint(a4[i]);
                unsigned long long ad;
                asm("mov.b64 %0, {%1, %1};" : "=l"(ad) : "r"(au));
                asm("fma.rn.f32x2 %0, %1, %2, %0;" : "+l"(accd[i][0]) : "l"(ad), "l"(bq0));
                asm("fma.rn.f32x2 %0, %1, %2, %0;" : "+l"(accd[i][1]) : "l"(ad), "l"(bq1));
                asm("fma.rn.f32x2 %0, %1, %2, %0;" : "+l"(accd[i][2]) : "l"(ad), "l"(bq2));
                asm("fma.rn.f32x2 %0, %1, %2, %0;" : "+l"(accd[i][3]) : "l"(ad), "l"(bq3));
            }
        }
        if (has) {
            int alt = cur ^ 1;
            As[alt][fk + 0][frow] = na.x; As[alt][fk + 1][frow] = na.y;
            As[alt][fk + 2][frow] = na.z; As[alt][fk + 3][frow] = na.w;
            Bs[alt][fk + 0][frow] = nb.x; Bs[alt][fk + 1][frow] = nb.y;
            Bs[alt][fk + 2][frow] = nb.z; Bs[alt][fk + 3][frow] = nb.w;
            __syncthreads();
            cur = alt;
        }
    }

    // unpack + store raw partials (mirror for off-diagonal tile)
    int r0 = tr * 128, c0 = tc * 128;
    #pragma unroll
    for (int i = 0; i < 8; i++) {
        int r = r0 + ((i < 4) ? (g * 4 + i) : (64 + g * 4 + i - 4));
        float vv[8];
        #pragma unroll
        for (int jp = 0; jp < 4; jp++) {
            unsigned int lo, hi;
            asm("mov.b64 {%0, %1}, %2;" : "=r"(lo), "=r"(hi) : "l"(accd[i][jp]));
            vv[2 * jp]     = __uint_as_float(lo);
            vv[2 * jp + 1] = __uint_as_float(hi);
        }
        float4 v0 = {vv[0], vv[1], vv[2], vv[3]};
        float4 v1 = {vv[4], vv[5], vv[6], vv[7]};
        *(float4*)&P[r * NT + c0 + h * 4] = v0;
        *(float4*)&P[r * NT + c0 + 64 + h * 4] = v1;
        if (tr != tc) {
            #pragma unroll
            for (int j = 0; j < 4; j++) P[(c0 + h * 4 + j) * NT + r] = vv[j];
            #pragma unroll
            for (int j = 0; j < 4; j++) P[(c0 + 64 + h * 4 + j) * NT + r] = vv[4 + j];
        }
    }
}

// ---------------- combine kernels ----------------
__global__ __launch_bounds__(256) void combine0_kernel() {
    int idx = blockIdx.x * blockDim.x + threadIdx.x;   // float4 index
    const float4* p0 = (const float4*)g_part[0];
    const float4* p1 = (const float4*)g_part[1];
    const float4* p2 = (const float4*)g_part[2];
    const float4* p3 = (const float4*)g_part[3];
    float4 a = p0[idx], b = p1[idx], c = p2[idx], d = p3[idx];
    float4 o;
    o.x = ((a.x + b.x) + c.x) + d.x;
    o.y = ((a.y + b.y) + c.y) + d.y;
    o.z = ((a.z + b.z) + c.z) + d.z;
    o.w = ((a.w + b.w) + c.w) + d.w;
    ((float4*)g_S)[idx] = o;
}

__global__ __launch_bounds__(256) void combine1_kernel() {
    int idx = blockIdx.x * blockDim.x + threadIdx.x;   // float4 index
    int c4 = idx & 63;
    int r = (idx >> 6) & 255;
    int b = idx >> 14;
    const float4* p0 = (const float4*)g_part[0];
    const float4* p1 = (const float4*)g_part[1];
    float4 t0 = p0[idx], t1 = p1[idx];
    float sqr = g_sq[b * NT + r];
    float4 sqc = ((const float4*)(g_sq + b * NT))[c4];
    float4 o;
    o.x = sqrtf(fmaxf(sqr + sqc.x - 2.f * (t0.x + t1.x), 0.f));
    o.y = sqrtf(fmaxf(sqr + sqc.y - 2.f * (t0.y + t1.y), 0.f));
    o.z = sqrtf(fmaxf(sqr + sqc.z - 2.f * (t0.z + t1.z), 0.f));
    o.w = sqrtf(fmaxf(sqr + sqc.w - 2.f * (t0.w + t1.w), 0.f));
    int cb = c4 * 4;
    if (r == cb + 0) o.x = BIGF;
    if (r == cb + 1) o.y = BIGF;
    if (r == cb + 2) o.z = BIGF;
    if (r == cb + 3) o.w = BIGF;
    ((float4*)g_Dm)[idx] = o;
}

// ---------------- 3: row sums of squares of S (warp per row) ----------------
__global__ void sqrow_kernel() {
    int R = blockIdx.x * 8 + (threadIdx.x >> 5);   // global row in [0, BN*NT)
    int lane = threadIdx.x & 31;
    const float4* S4 = (const float4*)(g_S + (size_t)R * NT);
    float4 a = S4[lane], b = S4[lane + 32];
    float s = a.x * a.x + a.y * a.y + a.z * a.z + a.w * a.w
            + b.x * b.x + b.y * b.y + b.z * b.z + b.w * b.w;
    #pragma unroll
    for (int o = 16; o; o >>= 1) s += __shfl_down_sync(0xffffffffu, s, o);
    if (lane == 0) g_sq[R] = s;
}

// ---------------- 4: clustering (one block per batch) ----------------
// Dead columns are written BIGF, so row scans need no activity mask.
__device__ __forceinline__ void row_scan4(const float* __restrict__ row,
                                          int lane, float& bv, int& bi) {
    const float4* r4 = (const float4*)row;
    float4 f0 = r4[lane];
    float4 f1 = r4[lane + 32];
    float v = f0.x; int idx = 4 * lane;
    if (f0.y < v) { v = f0.y; idx = 4 * lane + 1; }
    if (f0.z < v) { v = f0.z; idx = 4 * lane + 2; }
    if (f0.w < v) { v = f0.w; idx = 4 * lane + 3; }
    if (f1.x < v) { v = f1.x; idx = 128 + 4 * lane; }
    if (f1.y < v) { v = f1.y; idx = 128 + 4 * lane + 1; }
    if (f1.z < v) { v = f1.z; idx = 128 + 4 * lane + 2; }
    if (f1.w < v) { v = f1.w; idx = 128 + 4 * lane + 3; }
    #pragma unroll
    for (int o = 16; o; o >>= 1) {
        float ov = __shfl_down_sync(0xffffffffu, v, o);
        int oi = __shfl_down_sync(0xffffffffu, idx, o);
        if (ov < v || (ov == v && oi < idx)) { v = ov; idx = oi; }
    }
    bv = v; bi = idx;
}

__global__ __launch_bounds__(256) void cluster_kernel() {
    const int b = blockIdx.x;
    float* Dm = g_Dm + (size_t)b * NT * NT;
    const int t = threadIdx.x;
    const int lane = t & 31, wid = t >> 5;

    __shared__ __align__(16) float s_minv[NT];
    __shared__ short s_mini[NT];
    __shared__ float s_size[NT];
    __shared__ unsigned char s_active[NT];
    __shared__ short s_label[NT];
    __shared__ float s_wv[8];
    __shared__ int   s_wi[8];
    __shared__ int   s_recount;
    __shared__ short s_relist[NT];

    s_active[t] = 1; s_size[t] = 1.f; s_label[t] = (short)t;
    if (t == 0) s_recount = 0;
    __syncthreads();

    // initial per-row nearest neighbor (warp per row)
    for (int r = wid; r < NT; r += 8) {
        float v; int i2;
        row_scan4(Dm + (size_t)r * NT, lane, v, i2);
        if (lane == 0) { s_minv[r] = v; s_mini[r] = (short)i2; }
    }
    __syncthreads();

    for (int it = 0; it < NT - KC; ++it) {
        // --- every warp redundantly computes global argmin over s_minv ---
        int i;
        {
            const float4* m4 = (const float4*)s_minv;
            float4 f0 = m4[lane];
            float4 f1 = m4[lane + 32];
            float v = f0.x; int idx = 4 * lane;
            if (f0.y < v) { v = f0.y; idx = 4 * lane + 1; }
            if (f0.z < v) { v = f0.z; idx = 4 * lane + 2; }
            if (f0.w < v) { v = f0.w; idx = 4 * lane + 3; }
            if (f1.x < v) { v = f1.x; idx = 128 + 4 * lane; }
            if (f1.y < v) { v = f1.y; idx = 128 + 4 * lane + 1; }
            if (f1.z < v) { v = f1.z; idx = 128 + 4 * lane + 2; }
            if (f1.w < v) { v = f1.w; idx = 128 + 4 * lane + 3; }
            #pragma unroll
            for (int o = 16; o; o >>= 1) {
                float ov = __shfl_xor_sync(0xffffffffu, v, o);
                int oi = __shfl_xor_sync(0xffffffffu, idx, o);
                if (ov < v || (ov == v && oi < idx)) { v = ov; idx = oi; }
            }
            i = idx;
        }
        int j = s_mini[i];                          // i < j guaranteed
        float si = s_size[i], sj = s_size[j];
        float di = Dm[(size_t)i * NT + t];
        float dj = Dm[(size_t)j * NT + t];
        __syncthreads();                            // (A) reads done

        float nv = (si * di + sj * dj) / (si + sj);
        if (t == i) nv = BIGF;
        Dm[(size_t)i * NT + t] = nv;                // row i
        Dm[(size_t)t * NT + i] = nv;                // col i
        Dm[(size_t)t * NT + j] = BIGF;              // col j dead
        if (s_label[t] == (short)j) s_label[t] = (short)i;

        // row i's new rowmin from nv (block reduce, tie smallest col)
        {
            float cv = (t != i && t != j && s_active[t]) ? nv : BIGF;
            int ci = t;
            #pragma unroll
            for (int o = 16; o; o >>= 1) {
                float ov = __shfl_down_sync(0xffffffffu, cv, o);
                int oi = __shfl_down_sync(0xffffffffu, ci, o);
                if (ov < cv || (ov == cv && oi < ci)) { cv = ov; ci = oi; }
            }
            if (lane == 0) { s_wv[wid] = cv; s_wi[wid] = ci; }
        }
        if (t == 0) { s_size[i] = si + sj; s_active[j] = 0; s_minv[j] = BIGF; }

        // rowmin maintenance for other rows
        if (t != i && t != j && s_active[t]) {
            float mv = s_minv[t]; int mi = s_mini[t];
            if (mi == i || mi == j) {
                if (nv < mv) { s_minv[t] = nv; s_mini[t] = (short)i; }
                else { int p = atomicAdd(&s_recount, 1); s_relist[p] = (short)t; }
            } else if (nv < mv || (nv == mv && i < mi)) {
                s_minv[t] = nv; s_mini[t] = (short)i;
            }
        }
        __syncthreads();                            // (B) writes visible

        if (t == 0) {
            float bv = s_wv[0]; int bi2 = s_wi[0];
            #pragma unroll
            for (int w = 1; w < 8; w++)
                if (s_wv[w] < bv || (s_wv[w] == bv && s_wi[w] < bi2)) { bv = s_wv[w]; bi2 = s_wi[w]; }
            s_minv[i] = bv; s_mini[i] = (short)bi2;
        }
        int rc = s_recount;
        for (int e = wid; e < rc; e += 8) {
            int r2 = s_relist[e];
            float v2; int i2;
            row_scan4(Dm + (size_t)r2 * NT, lane, v2, i2);
            if (lane == 0) { s_minv[r2] = v2; s_mini[r2] = (short)i2; }
        }
        if (t == 0) s_recount = 0;
        __syncthreads();                            // (C) state ready
    }

    // canonical relabel: new_id = cumsum(active)-1
    __shared__ short s_newid[NT];
    __shared__ short s_flab[NT];
    __shared__ short s_cnt[KC];
    __shared__ short s_off[KC];
    {
        int c = 0;
        for (int r2 = 0; r2 <= t; ++r2) c += s_active[r2];
        s_newid[t] = (short)(c - 1);
    }
    __syncthreads();
    int fl = s_newid[s_label[t]];
    s_flab[t] = (short)fl;
    __syncthreads();
    if (t < KC) {
        int cnt = 0;
        for (int r2 = 0; r2 < NT; r2++) cnt += (s_flab[r2] == (short)t);
        s_cnt[t] = (short)cnt;
        g_ccnt[b * KC + t] = cnt;
    }
    __syncthreads();
    if (t < KC) {
        int off = 0;
        for (int k2 = 0; k2 < t; k2++) off += s_cnt[k2];
        s_off[t] = (short)off;
        g_coff[b * KC + t] = off;
    }
    __syncthreads();
    {
        int rank = 0;
        for (int r2 = 0; r2 < t; r2++) rank += (s_flab[r2] == (short)fl);
        g_order[b * NT + s_off[fl] + rank] = t;
    }
}

// ---------------- 5: mask (softmax) + sal_mass ----------------
__global__ void mask_kernel(const float* __restrict__ sal,
                            const float* __restrict__ gum,
                            float* __restrict__ mout) {
    int b = blockIdx.x, t = threadIdx.x;
    float s = sal[b * NT + t];
    float l = (s + gum[b * NT + t]) / 0.1f;
    __shared__ float red[8];
    float m = l;
    #pragma unroll
    for (int o = 16; o; o >>= 1) m = fmaxf(m, __shfl_xor_sync(0xffffffffu, m, o));
    if ((t & 31) == 0) red[t >> 5] = m;
    __syncthreads();
    float mx = red[0];
    #pragma unroll
    for (int w = 1; w < 8; w++) mx = fmaxf(mx, red[w]);
    float e = expf(l - mx);
    float sm = e;
    #pragma unroll
    for (int o = 16; o; o >>= 1) sm += __shfl_xor_sync(0xffffffffu, sm, o);
    __syncthreads();
    if ((t & 31) == 0) red[t >> 5] = sm;
    __syncthreads();
    float tot = 0.f;
    #pragma unroll
    for (int w = 0; w < 8; w++) tot += red[w];
    float mk = e / tot;
    mout[b * NT + t] = mk;
    g_salmass[b * NT + t] = mk * s + (1.f - mk) * 0.01f;
}

// ---------------- 6: saliency-weighted per-cluster merge ----------------
__global__ __launch_bounds__(256) void merge_kernel(const float* __restrict__ X,
                                                    float* __restrict__ out) {
    int b = blockIdx.x >> 6;
    int k = blockIdx.x & 63;
    int cnt = g_ccnt[b * KC + k];
    int off = g_coff[b * KC + k];
    int t = threadIdx.x;
    int d0 = t * 8;
    float acc[8] = {0.f, 0.f, 0.f, 0.f, 0.f, 0.f, 0.f, 0.f};
    float den = 0.f;
    for (int e = 0; e < cnt; ++e) {
        int tok = g_order[b * NT + off + e];
        float w = g_salmass[b * NT + tok];
        den += w;
        const float4* xp = (const float4*)(X + ((size_t)(b * NT + tok) * DD + d0));
        float4 x0 = xp[0], x1 = xp[1];
        acc[0] += w * x0.x; acc[1] += w * x0.y; acc[2] += w * x0.z; acc[3] += w * x0.w;
        acc[4] += w * x1.x; acc[5] += w * x1.y; acc[6] += w * x1.z; acc[7] += w * x1.w;
    }
    float d = den + 1e-8f;
    float4 o0, o1;
    o0.x = acc[0] / d; o0.y = acc[1] / d; o0.z = acc[2] / d; o0.w = acc[3] / d;
    o1.x = acc[4] / d; o1.y = acc[5] / d; o1.z = acc[6] / d; o1.w = acc[7] / d;
    float4* op = (float4*)(out + ((size_t)(b * KC + k) * DD + d0));
    op[0] = o0; op[1] = o1;
}

// ---------------- launch ----------------
extern "C" void kernel_launch(void* const* d_in, const int* in_sizes, int n_in,
                              void* d_out, int out_size) {
    const float* X = (const float*)d_in[0];
    const float* sal = (const float*)d_in[1];
    const float* gum = (const float*)d_in[2];
    float* out = (float*)d_out;

    const int MERGED = BN * KC * DD;           // 4,194,304
    float* mask_out;
    if (out_size >= MERGED + BN * NT) {
        mask_out = out + MERGED;
    } else {
        cudaError_t e; void* p = nullptr;
        e = cudaGetSymbolAddress(&p, g_maskdump);
        (void)e;
        mask_out = (float*)p;
    }

    const int NF4 = BN * NT * NT / 4;          // 524288 float4s

    rnorm_kernel<<<BN * NT / 8, 256>>>(X);
    gemm128<0, 4><<<dim3(3, BN, 4), 256>>>(X);
    combine0_kernel<<<NF4 / 256, 256>>>();
    sqrow_kernel<<<BN * NT / 8, 256>>>();
    gemm128<1, 2><<<dim3(3, BN, 2), 256>>>(nullptr);
    combine1_kernel<<<NF4 / 256, 256>>>();
    cluster_kernel<<<BN, 256>>>();
    mask_kernel<<<BN, 256>>>(sal, gum, mask_out);
    merge_kernel<<<BN * KC, 256>>>(X, out);
}